// round 13
// baseline (speedup 1.0000x reference)
#include <cuda_runtime.h>
#include <cuda_fp16.h>
#include <math.h>
#include <stdint.h>

#define NN   20000
#define EE   400000
#define ET   (EE + NN)
#define HH   10
#define FF   78
#define HID  780
#define NEXT 800
#define BB   200
#define SEQ  1000
#define VOC  26
#define EMB  128
#define NF   32
#define KS   8
#define COUT 993
#define KPA  128
#define KPG  832
#define DMAX 256
#define NB   79

// ---------------- scratch ----------------
__device__ __half g_hH [(long)NN * NEXT];
__device__ __half g_h2H[(long)NN * HID];
__device__ __half g_x2H[(long)NN * HID];
__device__ float g_asad[NN * 20];
__device__ float g_e  [(long)ET * HH];
__device__ float g_xg [BB * HID];
__device__ float g_t1 [BB * 1500];
__device__ float g_xc [BB * 256];
__device__ float g_t2 [BB * 1024];
__device__ float g_t3 [BB * 512];
__device__ float g_t4 [BB * 256];
__device__ float g_t5 [BB * 128];
__device__ float g_P  [VOC * NF * KS];
__device__ float g_R  [(long)VOC * SEQ * 128];
__device__ float g_biasY[128];
__device__ int   g_cnt[NN];        // invariant: zero at kernel_launch entry
__device__ int   g_off[NN + 1];
__device__ int   g_bsum[NB];
__device__ int   g_bpre[NB];
__device__ int   g_srcA[ET];
__device__ int   g_start[BB + 1];
__device__ float g_dinv[NN];
__device__ __half g_Axh[(long)NN * KPA];
__device__ __half g_Bah[(long)NEXT * KPA];
__device__ __half g_Ag [(long)NN * KPG];
__device__ __half g_Bgh[(long)HID * KPG];

// ---------------- helpers ----------------
__device__ __forceinline__ uint32_t smem_u32(const void* p) {
    uint32_t a;
    asm("{ .reg .u64 t; cvta.to.shared.u64 t, %1; cvt.u32.u64 %0, t; }" : "=r"(a) : "l"(p));
    return a;
}
__device__ __forceinline__ void cpasync16(uint32_t dst, const void* src, int nbytes) {
    asm volatile("cp.async.cg.shared.global [%0], [%1], 16, %2;"
                 :: "r"(dst), "l"(__cvta_generic_to_global(src)), "r"(nbytes) : "memory");
}
__device__ __forceinline__ void ldm4(uint32_t* r, uint32_t addr) {
    asm volatile("ldmatrix.sync.aligned.m8n8.x4.shared.b16 {%0,%1,%2,%3}, [%4];"
                 : "=r"(r[0]), "=r"(r[1]), "=r"(r[2]), "=r"(r[3]) : "r"(addr));
}
__device__ __forceinline__ void mma16816h(float* c, const uint32_t* a, uint32_t b0, uint32_t b1) {
    asm volatile("mma.sync.aligned.m16n8k16.row.col.f32.f16.f16.f32 "
                 "{%0,%1,%2,%3}, {%4,%5,%6,%7}, {%8,%9}, {%0,%1,%2,%3};"
                 : "+f"(c[0]), "+f"(c[1]), "+f"(c[2]), "+f"(c[3])
                 : "r"(a[0]), "r"(a[1]), "r"(a[2]), "r"(a[3]), "r"(b0), "r"(b1));
}

// ---------------- tiny init ----------------
__global__ void k_init0() {
    g_biasY[threadIdx.x] = 0.f;
}

// ---------------- prep ----------------
#define PB_A 10000
#define PB_E 20
__global__ void __launch_bounds__(256) k_prep(const float* __restrict__ x,
                                              const float* __restrict__ gat_W,
                                              const float* __restrict__ aS,
                                              const float* __restrict__ aD) {
    int bid = blockIdx.x, t = threadIdx.x;
    if (bid < PB_A) {
        int i = bid * 256 + t;
        int m = i >> 7, k = i & 127;
        g_Axh[i] = __float2half_rn(k < FF ? x[(long)m * FF + k] : 0.f);
    } else {
        int i = bid - PB_A;
        int k = t;
        if (k >= 128) return;
        int h = i % 10;
        const float* av = ((i < 10) ? aS : aD) + h * FF;
        float s = 0.f;
        if (k < FF) {
            const float* wr = gat_W + (long)k * HID + h * FF;
#pragma unroll 13
            for (int f = 0; f < FF; f++) s += wr[f] * av[f];
        }
        g_Bah[(long)(HID + i) * KPA + k] = __float2half_rn(s);
    }
}

// ---------------- coalesced transpose-convert ----------------
__global__ void __launch_bounds__(256) k_transW(const float* __restrict__ W,
                                                __half* __restrict__ dst,
                                                int K, int N, int Kp) {
    __shared__ float tile[32][33];
    int k0 = blockIdx.x * 32, n0 = blockIdx.y * 32;
    int tx = threadIdx.x & 31, ty = threadIdx.x >> 5;
#pragma unroll
    for (int r = 0; r < 4; r++) {
        int k = k0 + ty + r * 8, n = n0 + tx;
        tile[ty + r * 8][tx] = (k < K && n < N) ? W[(long)k * N + n] : 0.f;
    }
    __syncthreads();
#pragma unroll
    for (int r = 0; r < 4; r++) {
        int n = n0 + ty + r * 8, k = k0 + tx;
        if (n < N && k < Kp)
            dst[(long)n * Kp + k] = __float2half_rn(tile[tx][ty + r * 8]);
    }
}

// ============ fp16 tensor-core GEMM, KC=64, 3-stage, fragment-pipelined ============
#define KC 64
#define ASTR 72
#define HALF_BYTES (128 * ASTR * 2)
#define STAGE_BYTES (2 * HALF_BYTES)
#define GEMM_SMEM (3 * STAGE_BYTES)

__global__ void __launch_bounds__(256)
gemm_mma(const __half* __restrict__ Ah, const __half* __restrict__ Bh,
         __half* __restrict__ C, int M, int N, int Kp, int NC, int ldc,
         float* __restrict__ aux, int auxcol) {
    extern __shared__ char smem_raw[];
    uint32_t sb = smem_u32(smem_raw);
    int tid = threadIdx.x, w = tid >> 5, l = tid & 31;
    int m0 = blockIdx.y * 128, n0 = blockIdx.x * 128;
    int wm = w & 3, wn = w >> 2;

    float acc[2][8][4];
#pragma unroll
    for (int i = 0; i < 2; i++)
#pragma unroll
        for (int j = 0; j < 8; j++)
#pragma unroll
            for (int q = 0; q < 4; q++) acc[i][j][q] = 0.f;

    auto issue = [&](int c) {
        int k0 = c * KC;
        uint32_t st = sb + (uint32_t)(c % 3) * STAGE_BYTES;
#pragma unroll
        for (int p = 0; p < 4; p++) {
            int f = tid + p * 256;
            int row = f >> 3, c16 = f & 7;
            uint32_t doff = (uint32_t)(row * (ASTR * 2) + c16 * 16);
            int am = m0 + row;
            int amc = am < M ? am : M - 1;
            int av = am < M ? 16 : 0;
            cpasync16(st + doff, Ah + (long)amc * Kp + k0 + c16 * 8, av);
            int bn = n0 + row;
            int bnc = bn < N ? bn : N - 1;
            int bv = bn < N ? 16 : 0;
            cpasync16(st + HALF_BYTES + doff, Bh + (long)bnc * Kp + k0 + c16 * 8, bv);
        }
        asm volatile("cp.async.commit_group;" ::: "memory");
    };

    int lrow = l & 15, lcb = l >> 4;
    uint32_t bhf[2][4][4], ahf[2][2][4];
    auto loadFrag = [&](int k16, int buf, uint32_t st) {
        uint32_t coff = (uint32_t)((k16 * 16 + lcb * 8) * 2);
#pragma unroll
        for (int nt2 = 0; nt2 < 4; nt2++) {
            uint32_t roff = (uint32_t)((wn * 64 + nt2 * 16 + lrow) * (ASTR * 2));
            ldm4(bhf[buf][nt2], st + HALF_BYTES + roff + coff);
        }
#pragma unroll
        for (int mt = 0; mt < 2; mt++) {
            uint32_t roff = (uint32_t)((wm * 32 + mt * 16 + lrow) * (ASTR * 2));
            ldm4(ahf[buf][mt], st + roff + coff);
        }
    };

    issue(0);
    if (NC > 1) issue(1);
    for (int c = 0; c < NC; c++) {
        if (c + 1 < NC) asm volatile("cp.async.wait_group 1;" ::: "memory");
        else            asm volatile("cp.async.wait_group 0;" ::: "memory");
        __syncthreads();
        if (c + 2 < NC) issue(c + 2);
        uint32_t st = sb + (uint32_t)(c % 3) * STAGE_BYTES;
        loadFrag(0, 0, st);
#pragma unroll
        for (int k16 = 0; k16 < 4; k16++) {
            int cur = k16 & 1;
            if (k16 < 3) loadFrag(k16 + 1, cur ^ 1, st);
#pragma unroll
            for (int mt = 0; mt < 2; mt++) {
#pragma unroll
                for (int nt = 0; nt < 8; nt++) {
                    int nt2 = nt >> 1, sel = nt & 1;
                    mma16816h(acc[mt][nt], ahf[cur][mt], bhf[cur][nt2][sel], bhf[cur][nt2][sel + 2]);
                }
            }
        }
        __syncthreads();
    }

#pragma unroll
    for (int mt = 0; mt < 2; mt++) {
#pragma unroll
        for (int nt = 0; nt < 8; nt++) {
            int row = m0 + wm * 32 + mt * 16 + (l >> 2);
            int col = n0 + wn * 64 + nt * 8 + 2 * (l & 3);
            if (col < N) {
                if (col >= auxcol) {
                    int ac = col - auxcol;
                    if (row < M) {
                        aux[row * 20 + ac]     = acc[mt][nt][0];
                        aux[row * 20 + ac + 1] = acc[mt][nt][1];
                    }
                    int row2 = row + 8;
                    if (row2 < M) {
                        aux[row2 * 20 + ac]     = acc[mt][nt][2];
                        aux[row2 * 20 + ac + 1] = acc[mt][nt][3];
                    }
                } else {
                    if (row < M)
                        *(__half2*)(C + (long)row * ldc + col) =
                            __floats2half2_rn(acc[mt][nt][0], acc[mt][nt][1]);
                    int row2 = row + 8;
                    if (row2 < M)
                        *(__half2*)(C + (long)row2 * ldc + col) =
                            __floats2half2_rn(acc[mt][nt][2], acc[mt][nt][3]);
                }
            }
        }
    }
}

// ---------------- latency-optimized skinny GEMM ----------------
__global__ void __launch_bounds__(256)
mlp8(const float* __restrict__ A, const float* __restrict__ W,
     float* __restrict__ C, const float* __restrict__ bias,
     int M, int N, int K, int lda, int ldc, int coff, int relu) {
    __shared__ float sact[8 * 1504];
    int t = threadIdx.x;
    int j = t & 63, kc = t >> 6;
    int jg = blockIdx.x * 64 + j;
    int r0 = blockIdx.y * 8;

    for (int i = t; i < 8 * K; i += 256) {
        int r = i / K, k = i - r * K;
        int row = r0 + r;
        sact[i] = (row < M) ? A[(long)row * lda + k] : 0.f;
    }
    __syncthreads();

    float acc[8];
#pragma unroll
    for (int r = 0; r < 8; r++) acc[r] = 0.f;
    if (jg < N) {
        for (int k = kc; k < K; k += 4) {
            float wv = W[(long)k * N + jg];
            const float* ar = &sact[k];
#pragma unroll
            for (int r = 0; r < 8; r++) acc[r] += ar[r * K] * wv;
        }
    }
    __syncthreads();
    float* red = sact;
#pragma unroll
    for (int r = 0; r < 8; r++) red[(j * 4 + kc) + r * 256] = acc[r];
    __syncthreads();
    if (kc == 0 && jg < N) {
        float b = bias ? bias[jg] : 0.f;
#pragma unroll
        for (int r = 0; r < 8; r++) {
            int row = r0 + r;
            if (row >= M) break;
            float v = red[j * 4 + r * 256] + red[j * 4 + 1 + r * 256]
                    + red[j * 4 + 2 + r * 256] + red[j * 4 + 3 + r * 256] + b;
            if (relu) v = fmaxf(v, 0.f);
            C[(long)row * ldc + coff + jg] = v;
        }
    }
}

// ---------------- CSR build ----------------
__global__ void k_count(const int* __restrict__ edge) {
    int i = blockIdx.x * blockDim.x + threadIdx.x;
    if (i >= ET) return;
    int dst = (i < EE) ? edge[EE + i] : i - EE;
    atomicAdd(&g_cnt[dst], 1);
}
__global__ void __launch_bounds__(256) k_scanA() {
    __shared__ int s[256];
    int t = threadIdx.x;
    int i = blockIdx.x * 256 + t;
    s[t] = (i < NN) ? g_cnt[i] : 0;
    __syncthreads();
    for (int off = 128; off > 0; off >>= 1) {
        if (t < off) s[t] += s[t + off];
        __syncthreads();
    }
    if (t == 0) g_bsum[blockIdx.x] = s[0];
}
__global__ void k_scanB() {
    __shared__ int s[NB];
    int t = threadIdx.x;
    if (t < NB) s[t] = g_bsum[t];
    __syncthreads();
    if (t == 0) {
        int r = 0;
        for (int i = 0; i < NB; i++) { int v = s[i]; g_bpre[i] = r; r += v; }
        g_off[NN] = r;
    }
}
__global__ void __launch_bounds__(256) k_scanC() {
    __shared__ int s[256];
    int t = threadIdx.x;
    int i = blockIdx.x * 256 + t;
    int c = (i < NN) ? g_cnt[i] : 0;
    s[t] = c;
    __syncthreads();
    for (int off = 1; off < 256; off <<= 1) {
        int v = (t >= off) ? s[t - off] : 0;
        __syncthreads();
        s[t] += v;
        __syncthreads();
    }
    if (i < NN) {
        g_off[i] = g_bpre[blockIdx.x] + s[t] - c;
        g_dinv[i] = rsqrtf((float)(c > 0 ? c : 1));
    }
}
__global__ void k_scatter(const int* __restrict__ edge) {
    int i = blockIdx.x * blockDim.x + threadIdx.x;
    if (i >= ET) return;
    int src = (i < EE) ? edge[i]      : i - EE;
    int dst = (i < EE) ? edge[EE + i] : i - EE;
    int old = atomicSub(&g_cnt[dst], 1);
    g_srcA[g_off[dst] + old - 1] = src;
}
__global__ void k_startB(const int* __restrict__ batch) {
    int n = blockIdx.x * blockDim.x + threadIdx.x;
    if (n >= NN) return;
    int b = batch[n];
    if (n == 0) {
        for (int bb = 0; bb <= b; bb++) g_start[bb] = 0;
    } else {
        int pb = batch[n - 1];
        if (pb != b) for (int bb = pb + 1; bb <= b; bb++) g_start[bb] = n;
    }
    if (n == NN - 1) {
        for (int bb = b + 1; bb <= BB; bb++) g_start[bb] = NN;
    }
}

// ---------------- fused softmax + GAT aggregation ----------------
__device__ __forceinline__ uint32_t fmapU(float f) {
    uint32_t u = __float_as_uint(f);
    return u ^ (uint32_t)(((int)u >> 31) | 0x80000000);
}
__device__ __forceinline__ float finvU(uint32_t u) {
    return (u & 0x80000000u) ? __uint_as_float(u ^ 0x80000000u) : __uint_as_float(~u);
}
__global__ void __launch_bounds__(256) k_gat_soft_agg(const float* __restrict__ gat_b) {
    __shared__ float sal[DMAX * HH];
    __shared__ int ssrc[DMAX];
    __shared__ uint32_t sm[HH];
    __shared__ float sden[HH], sad[HH];
    int n = blockIdx.x, t = threadIdx.x;
    int lo = g_off[n], d = g_off[n + 1] - lo;
    bool small = (d <= DMAX);
    float* ebuf = small ? sal : &g_e[(long)lo * HH];
    const int* sp = small ? ssrc : &g_srcA[lo];
    if (t < HH) { sm[t] = fmapU(-INFINITY); sden[t] = 0.f; sad[t] = g_asad[n * 20 + 10 + t]; }
    if (small)
        for (int i = t; i < d; i += 256) ssrc[i] = g_srcA[lo + i];
    __syncthreads();
    int tot = d * HH;
    for (int p = t; p < tot; p += 256) {
        int i = p / HH, h = p - i * HH;
        int src = sp[i];
        float e = g_asad[src * 20 + h] + sad[h];
        e = (e > 0.f) ? e : 0.2f * e;
        ebuf[p] = e;
        atomicMax(&sm[h], fmapU(e));
    }
    __syncthreads();
    for (int p = t; p < tot; p += 256) {
        int h = p % HH;
        float ex = expf(ebuf[p] - finvU(sm[h]));
        ebuf[p] = ex;
        atomicAdd(&sden[h], ex);
    }
    __syncthreads();
    if (t < HH) sden[t] = 1.f / sden[t];
    __syncthreads();

    if (t >= 208) return;
    long base = (long)n * KPG + t * 4;
    if (t >= 195) {
        __half2 z = __floats2half2_rn(0.f, 0.f);
        *(__half2*)(g_Ag + base) = z;
        *(__half2*)(g_Ag + base + 2) = z;
        return;
    }
    int q = t * 4;
    int h0 = q / FF, h1 = (q + 1) / FF, h2 = (q + 2) / FF, h3 = (q + 3) / FF;
    float ax = 0.f, ay = 0.f, az = 0.f, aw = 0.f;
    for (int idx = 0; idx < d; idx++) {
        int s = sp[idx];
        uint2 u = *(const uint2*)(g_hH + (long)s * NEXT + q);
        float2 v01 = __half22float2(*(__half2*)&u.x);
        float2 v23 = __half22float2(*(__half2*)&u.y);
        const float* al = &ebuf[idx * HH];
        ax += v01.x * al[h0]; ay += v01.y * al[h1]; az += v23.x * al[h2]; aw += v23.y * al[h3];
    }
    ax *= sden[h0]; ay *= sden[h1]; az *= sden[h2]; aw *= sden[h3];
    float v0 = fmaxf(ax + gat_b[q + 0], 0.f);
    float v1 = fmaxf(ay + gat_b[q + 1], 0.f);
    float v2 = fmaxf(az + gat_b[q + 2], 0.f);
    float v3 = fmaxf(aw + gat_b[q + 3], 0.f);
    *(__half2*)(g_Ag + base)     = __floats2half2_rn(v0, v1);
    *(__half2*)(g_Ag + base + 2) = __floats2half2_rn(v2, v3);
}

// ---------------- GCN aggregation ----------------
__global__ void __launch_bounds__(256) k_gcn_agg(const float* __restrict__ gcn_b) {
    int n = blockIdx.x, t = threadIdx.x;
    if (t >= 195) return;
    int q = t * 4;
    float dn = g_dinv[n];
    float ax = 0.f, ay = 0.f, az = 0.f, aw = 0.f;
    int lo = g_off[n], hi = g_off[n + 1];
    for (int idx = lo; idx < hi; idx++) {
        int s = g_srcA[idx];
        float norm = dn * g_dinv[s];
        uint2 u = *(const uint2*)(g_h2H + (long)s * HID + q);
        float2 v01 = __half22float2(*(__half2*)&u.x);
        float2 v23 = __half22float2(*(__half2*)&u.y);
        ax += v01.x * norm; ay += v01.y * norm; az += v23.x * norm; aw += v23.y * norm;
    }
    float v0 = fmaxf(ax + gcn_b[q + 0], 0.f);
    float v1 = fmaxf(ay + gcn_b[q + 1], 0.f);
    float v2 = fmaxf(az + gcn_b[q + 2], 0.f);
    float v3 = fmaxf(aw + gcn_b[q + 3], 0.f);
    *(__half2*)(g_x2H + (long)n * HID + q)     = __floats2half2_rn(v0, v1);
    *(__half2*)(g_x2H + (long)n * HID + q + 2) = __floats2half2_rn(v2, v3);
}

// ---------------- segment pool ----------------
__global__ void __launch_bounds__(256) k_pool() {
    int b = blockIdx.x, t = threadIdx.x;
    if (t >= 195) return;
    int q = t * 4;
    int lo = g_start[b], hi = g_start[b + 1];
    float ax = 0.f, ay = 0.f, az = 0.f, aw = 0.f;
    for (int n = lo; n < hi; n++) {
        uint2 u = *(const uint2*)(g_x2H + (long)n * HID + q);
        float2 v01 = __half22float2(*(__half2*)&u.x);
        float2 v23 = __half22float2(*(__half2*)&u.y);
        ax += v01.x; ay += v01.y; az += v23.x; aw += v23.y;
    }
    float* o = g_xg + (long)b * HID + q;
    o[0] = ax; o[1] = ay; o[2] = az; o[3] = aw;
}

// ---------------- protein branch ----------------
__global__ void k_Pbias(const float* __restrict__ emb, const float* __restrict__ cW,
                        const float* __restrict__ fxtW, const float* __restrict__ cb) {
    int bi = blockIdx.x, j = threadIdx.x;
    if (bi < 256) {
        int o = bi >> 3, c = bi & 7;
        int t0 = c * 125, t1 = min(t0 + 125, COUT);
        float p = 0.f;
        for (int t = t0; t < t1; t++)
            p += fxtW[((long)(o * COUT + t)) * 128 + j];
        atomicAdd(&g_biasY[j], cb[o] * p);
    } else {
        int g = (bi - 256) * 128 + j;
        if (g >= VOC * NF * KS) return;
        int v = g / (NF * KS), r = g % (NF * KS);
        int o = r / KS, k = r % KS;
        float s = 0.f;
#pragma unroll 16
        for (int e = 0; e < EMB; e++)
            s += emb[v * EMB + e] * cW[o * EMB * KS + e * KS + k];
        g_P[g] = s;
    }
}
__global__ void k_R(const float* __restrict__ fxtW) {
    __shared__ float Ps[VOC * NF * KS];
    int s = blockIdx.x, j = threadIdx.x;
    for (int idx = j; idx < VOC * NF * KS; idx += 128) Ps[idx] = g_P[idx];
    __syncthreads();
    float acc[VOC];
#pragma unroll
    for (int v = 0; v < VOC; v++) acc[v] = 0.f;
    int kmin = (s > COUT - 1) ? (s - (COUT - 1)) : 0;
    int kmax = (s < KS - 1) ? s : (KS - 1);
    for (int o = 0; o < NF; o++) {
        for (int k = kmin; k <= kmax; k++) {
            float w = fxtW[((long)(o * COUT + s - k)) * 128 + j];
#pragma unroll
            for (int v = 0; v < VOC; v++)
                acc[v] += Ps[v * (NF * KS) + o * KS + k] * w;
        }
    }
#pragma unroll
    for (int v = 0; v < VOC; v++)
        g_R[((long)v * SEQ + s) * 128 + j] = acc[v];
}
__global__ void k_Y(const int* __restrict__ target, const float* __restrict__ fxt_b) {
    __shared__ int sv[SEQ];
    int b = blockIdx.x, j = threadIdx.x;
    for (int i = j; i < SEQ; i += 128) sv[i] = target[b * SEQ + i];
    __syncthreads();
    float acc = g_biasY[j] + fxt_b[j];
    for (int s = 0; s < SEQ; s += 4) {
        float r0 = g_R[((long)sv[s]     * SEQ + s)     * 128 + j];
        float r1 = g_R[((long)sv[s + 1] * SEQ + s + 1) * 128 + j];
        float r2 = g_R[((long)sv[s + 2] * SEQ + s + 2) * 128 + j];
        float r3 = g_R[((long)sv[s + 3] * SEQ + s + 3) * 128 + j];
        acc += (r0 + r1) + (r2 + r3);
    }
    g_xc[b * 256 + 128 + j] = acc;
}

// ---------------- output ----------------
__global__ void k_out(const float* __restrict__ oW, const float* __restrict__ ob,
                      float* __restrict__ out) {
    __shared__ float red[4];
    int b = blockIdx.x, j = threadIdx.x;
    float v = g_t5[b * 128 + j] * oW[j];
#pragma unroll
    for (int off = 16; off; off >>= 1) v += __shfl_down_sync(0xffffffffu, v, off);
    if ((j & 31) == 0) red[j >> 5] = v;
    __syncthreads();
    if (j == 0) out[b] = red[0] + red[1] + red[2] + red[3] + ob[0];
}

// ---------------- host ----------------
static inline dim3 ggrid(long n, int t) { return dim3((unsigned)((n + t - 1) / t)); }

extern "C" void kernel_launch(void* const* d_in, const int* in_sizes, int n_in,
                              void* d_out, int out_size) {
    const float* x      = (const float*)d_in[0];
    const int*   edge   = (const int*)  d_in[1];
    const int*   batch  = (const int*)  d_in[2];
    const int*   target = (const int*)  d_in[3];
    const float* gat_W  = (const float*)d_in[4];
    const float* a_src  = (const float*)d_in[5];
    const float* a_dst  = (const float*)d_in[6];
    const float* gat_b  = (const float*)d_in[7];
    const float* gcn_W  = (const float*)d_in[8];
    const float* gcn_b  = (const float*)d_in[9];
    const float* fcg1_W = (const float*)d_in[10];
    const float* fcg1_b = (const float*)d_in[11];
    const float* fcg2_W = (const float*)d_in[12];
    const float* fcg2_b = (const float*)d_in[13];
    const float* emb    = (const float*)d_in[14];
    const float* cW     = (const float*)d_in[15];
    const float* cb     = (const float*)d_in[16];
    const float* fxt_W  = (const float*)d_in[17];
    const float* fxt_b  = (const float*)d_in[18];
    const float* f1_W   = (const float*)d_in[19];
    const float* f1_b   = (const float*)d_in[20];
    const float* f2_W   = (const float*)d_in[21];
    const float* f2_b   = (const float*)d_in[22];
    const float* f3_W   = (const float*)d_in[23];
    const float* f3_b   = (const float*)d_in[24];
    const float* f4_W   = (const float*)d_in[25];
    const float* f4_b   = (const float*)d_in[26];
    const float* o_W    = (const float*)d_in[27];
    const float* o_b    = (const float*)d_in[28];
    float* out = (float*)d_out;

    float *p_xg, *p_t1, *p_xc, *p_t2, *p_t3, *p_t4, *p_t5, *p_asad;
    __half *p_hH, *p_h2H, *p_Axh, *p_Bah, *p_Ag, *p_Bgh;
    cudaGetSymbolAddress((void**)&p_hH,  g_hH);
    cudaGetSymbolAddress((void**)&p_h2H, g_h2H);
    cudaGetSymbolAddress((void**)&p_asad, g_asad);
    cudaGetSymbolAddress((void**)&p_xg,  g_xg);
    cudaGetSymbolAddress((void**)&p_t1,  g_t1);
    cudaGetSymbolAddress((void**)&p_xc,  g_xc);
    cudaGetSymbolAddress((void**)&p_t2,  g_t2);
    cudaGetSymbolAddress((void**)&p_t3,  g_t3);
    cudaGetSymbolAddress((void**)&p_t4,  g_t4);
    cudaGetSymbolAddress((void**)&p_t5,  g_t5);
    cudaGetSymbolAddress((void**)&p_Axh, g_Axh);
    cudaGetSymbolAddress((void**)&p_Bah, g_Bah);
    cudaGetSymbolAddress((void**)&p_Ag,  g_Ag);
    cudaGetSymbolAddress((void**)&p_Bgh, g_Bgh);

    static cudaStream_t s1, s2;
    static cudaEvent_t eF, e1, e2;
    static int inited = 0;
    if (!inited) {
        cudaStreamCreateWithFlags(&s1, cudaStreamNonBlocking);
        cudaStreamCreateWithFlags(&s2, cudaStreamNonBlocking);
        cudaEventCreateWithFlags(&eF, cudaEventDisableTiming);
        cudaEventCreateWithFlags(&e1, cudaEventDisableTiming);
        cudaEventCreateWithFlags(&e2, cudaEventDisableTiming);
        cudaFuncSetAttribute(gemm_mma, cudaFuncAttributeMaxDynamicSharedMemorySize, GEMM_SMEM);
        inited = 1;
    }

    cudaEventRecord(eF, 0);
    cudaStreamWaitEvent(s1, eF, 0);
    cudaStreamWaitEvent(s2, eF, 0);

    // main: conversions + attn rows
    k_transW<<<dim3(4, 25), 256>>>(gat_W, p_Bah, FF, HID, KPA);
    k_transW<<<dim3(26, 25), 256>>>(gcn_W, p_Bgh, HID, HID, KPG);
    k_prep<<<PB_A + PB_E, 256>>>(x, gat_W, a_src, a_dst);
    // s1: CSR build
    k_count<<<ggrid(ET, 256), 256, 0, s1>>>(edge);
    k_startB<<<ggrid(NN, 256), 256, 0, s1>>>(batch);
    k_scanA<<<NB, 256, 0, s1>>>();
    k_scanB<<<1, 128, 0, s1>>>();
    k_scanC<<<NB, 256, 0, s1>>>();
    // main: GAT GEMM
    gemm_mma<<<dim3(7, 157), 256, GEMM_SMEM>>>(p_Axh, p_Bah, p_hH, NN, NEXT, KPA, KPA / KC, NEXT,
                                               p_asad, HID);
    // s1: scatter
    k_scatter<<<ggrid(ET, 256), 256, 0, s1>>>(edge);
    cudaEventRecord(e1, s1);
    // s2: protein branch
    k_init0<<<1, 128, 0, s2>>>();
    k_Pbias<<<308, 128, 0, s2>>>(emb, cW, fxt_W, cb);
    k_R<<<SEQ, 128, 0, s2>>>(fxt_W);
    k_Y<<<BB, 128, 0, s2>>>(target, fxt_b);
    cudaEventRecord(e2, s2);
    // main: graph branch
    cudaStreamWaitEvent(0, e1, 0);
    k_gat_soft_agg<<<NN, 256>>>(gat_b);
    gemm_mma<<<dim3(7, 157), 256, GEMM_SMEM>>>(p_Ag, p_Bgh, p_h2H, NN, HID, KPG, KPG / KC, HID,
                                               nullptr, 1 << 30);
    k_gcn_agg<<<NN, 256>>>(gcn_b);
    k_pool<<<BB, 256>>>();
    // head
    mlp8<<<dim3(24, 25), 256>>>(p_xg, fcg1_W, p_t1, fcg1_b, BB, 1500, HID, HID, 1500, 0, 1);
    mlp8<<<dim3(2, 25), 256>>>(p_t1, fcg2_W, p_xc, fcg2_b, BB, 128, 1500, 1500, 256, 0, 0);
    cudaStreamWaitEvent(0, e2, 0);
    mlp8<<<dim3(16, 25), 256>>>(p_xc, f1_W, p_t2, f1_b, BB, 1024, 256, 256, 1024, 0, 1);
    mlp8<<<dim3(8, 25), 256>>>(p_t2, f2_W, p_t3, f2_b, BB, 512, 1024, 1024, 512, 0, 1);
    mlp8<<<dim3(4, 25), 256>>>(p_t3, f3_W, p_t4, f3_b, BB, 256, 512, 512, 256, 0, 1);
    mlp8<<<dim3(2, 25), 256>>>(p_t4, f4_W, p_t5, f4_b, BB, 128, 256, 256, 128, 0, 1);
    k_out<<<BB, 128>>>(o_W, o_b, out);
}

// round 14
// speedup vs baseline: 1.0160x; 1.0160x over previous
#include <cuda_runtime.h>
#include <cuda_fp16.h>
#include <math.h>
#include <stdint.h>

#define NN   20000
#define EE   400000
#define ET   (EE + NN)
#define HH   10
#define FF   78
#define HID  780
#define NEXT 800
#define BB   200
#define SEQ  1000
#define VOC  26
#define EMB  128
#define NF   32
#define KS   8
#define COUT 993
#define KPA  128
#define KPG  832
#define DMAX 256
#define NB   79

// ---------------- scratch ----------------
__device__ __half g_hH [(long)NN * NEXT];
__device__ __half g_h2H[(long)NN * HID];
__device__ __half g_x2H[(long)NN * HID];
__device__ float g_asad[NN * 20];
__device__ float g_e  [(long)ET * HH];
__device__ float g_xg [BB * HID];
__device__ float g_t1 [BB * 1500];
__device__ float g_xc [BB * 256];
__device__ float g_t2 [BB * 1024];
__device__ float g_t3 [BB * 512];
__device__ float g_t4 [BB * 256];
__device__ float g_t5 [BB * 128];
__device__ float g_P  [VOC * NF * KS];
__device__ float g_R  [(long)VOC * SEQ * 128];
__device__ float g_biasY[128];
__device__ int   g_cnt[NN];        // invariant: zero at kernel_launch entry
__device__ int   g_off[NN + 1];
__device__ int   g_bsum[NB];
__device__ int   g_bpre[NB];
__device__ int   g_srcA[ET];
__device__ int   g_start[BB + 1];
__device__ float g_dinv[NN];
__device__ __half g_Axh[(long)NN * KPA];
__device__ __half g_Bah[(long)NEXT * KPA];
__device__ __half g_Ag [(long)NN * KPG];
__device__ __half g_Bgh[(long)HID * KPG];

// ---------------- helpers ----------------
__device__ __forceinline__ uint32_t smem_u32(const void* p) {
    uint32_t a;
    asm("{ .reg .u64 t; cvta.to.shared.u64 t, %1; cvt.u32.u64 %0, t; }" : "=r"(a) : "l"(p));
    return a;
}
__device__ __forceinline__ void cpasync16(uint32_t dst, const void* src, int nbytes) {
    asm volatile("cp.async.cg.shared.global [%0], [%1], 16, %2;"
                 :: "r"(dst), "l"(__cvta_generic_to_global(src)), "r"(nbytes) : "memory");
}
__device__ __forceinline__ void ldm4(uint32_t* r, uint32_t addr) {
    asm volatile("ldmatrix.sync.aligned.m8n8.x4.shared.b16 {%0,%1,%2,%3}, [%4];"
                 : "=r"(r[0]), "=r"(r[1]), "=r"(r[2]), "=r"(r[3]) : "r"(addr));
}
__device__ __forceinline__ void mma16816h(float* c, const uint32_t* a, uint32_t b0, uint32_t b1) {
    asm volatile("mma.sync.aligned.m16n8k16.row.col.f32.f16.f16.f32 "
                 "{%0,%1,%2,%3}, {%4,%5,%6,%7}, {%8,%9}, {%0,%1,%2,%3};"
                 : "+f"(c[0]), "+f"(c[1]), "+f"(c[2]), "+f"(c[3])
                 : "r"(a[0]), "r"(a[1]), "r"(a[2]), "r"(a[3]), "r"(b0), "r"(b1));
}

// ---------------- tiny init ----------------
__global__ void k_init0() {
    g_biasY[threadIdx.x] = 0.f;
}

// ---------------- prep ----------------
#define PB_A 10000
#define PB_E 20
__global__ void __launch_bounds__(256) k_prep(const float* __restrict__ x,
                                              const float* __restrict__ gat_W,
                                              const float* __restrict__ aS,
                                              const float* __restrict__ aD) {
    int bid = blockIdx.x, t = threadIdx.x;
    if (bid < PB_A) {
        int i = bid * 256 + t;
        int m = i >> 7, k = i & 127;
        g_Axh[i] = __float2half_rn(k < FF ? x[(long)m * FF + k] : 0.f);
    } else {
        int i = bid - PB_A;
        int k = t;
        if (k >= 128) return;
        int h = i % 10;
        const float* av = ((i < 10) ? aS : aD) + h * FF;
        float s = 0.f;
        if (k < FF) {
            const float* wr = gat_W + (long)k * HID + h * FF;
#pragma unroll 13
            for (int f = 0; f < FF; f++) s += wr[f] * av[f];
        }
        g_Bah[(long)(HID + i) * KPA + k] = __float2half_rn(s);
    }
}

// ---------------- coalesced transpose-convert ----------------
__global__ void __launch_bounds__(256) k_transW(const float* __restrict__ W,
                                                __half* __restrict__ dst,
                                                int K, int N, int Kp) {
    __shared__ float tile[32][33];
    int k0 = blockIdx.x * 32, n0 = blockIdx.y * 32;
    int tx = threadIdx.x & 31, ty = threadIdx.x >> 5;
#pragma unroll
    for (int r = 0; r < 4; r++) {
        int k = k0 + ty + r * 8, n = n0 + tx;
        tile[ty + r * 8][tx] = (k < K && n < N) ? W[(long)k * N + n] : 0.f;
    }
    __syncthreads();
#pragma unroll
    for (int r = 0; r < 4; r++) {
        int n = n0 + ty + r * 8, k = k0 + tx;
        if (n < N && k < Kp)
            dst[(long)n * Kp + k] = __float2half_rn(tile[tx][ty + r * 8]);
    }
}

// ============ fp16 tensor-core GEMM, KC=64, 3-stage cp.async pipeline ============
#define KC 64
#define ASTR 72
#define HALF_BYTES (128 * ASTR * 2)
#define STAGE_BYTES (2 * HALF_BYTES)
#define GEMM_SMEM (3 * STAGE_BYTES)

__global__ void __launch_bounds__(256)
gemm_mma(const __half* __restrict__ Ah, const __half* __restrict__ Bh,
         __half* __restrict__ C, int M, int N, int Kp, int NC, int ldc,
         float* __restrict__ aux, int auxcol) {
    extern __shared__ char smem_raw[];
    uint32_t sb = smem_u32(smem_raw);
    int tid = threadIdx.x, w = tid >> 5, l = tid & 31;
    int m0 = blockIdx.y * 128, n0 = blockIdx.x * 128;
    int wm = w & 3, wn = w >> 2;

    float acc[2][8][4];
#pragma unroll
    for (int i = 0; i < 2; i++)
#pragma unroll
        for (int j = 0; j < 8; j++)
#pragma unroll
            for (int q = 0; q < 4; q++) acc[i][j][q] = 0.f;

    auto issue = [&](int c) {
        int k0 = c * KC;
        uint32_t st = sb + (uint32_t)(c % 3) * STAGE_BYTES;
#pragma unroll
        for (int p = 0; p < 4; p++) {
            int f = tid + p * 256;
            int row = f >> 3, c16 = f & 7;
            uint32_t doff = (uint32_t)(row * (ASTR * 2) + c16 * 16);
            int am = m0 + row;
            int amc = am < M ? am : M - 1;
            int av = am < M ? 16 : 0;
            cpasync16(st + doff, Ah + (long)amc * Kp + k0 + c16 * 8, av);
            int bn = n0 + row;
            int bnc = bn < N ? bn : N - 1;
            int bv = bn < N ? 16 : 0;
            cpasync16(st + HALF_BYTES + doff, Bh + (long)bnc * Kp + k0 + c16 * 8, bv);
        }
        asm volatile("cp.async.commit_group;" ::: "memory");
    };

    issue(0);
    if (NC > 1) issue(1);
    for (int c = 0; c < NC; c++) {
        if (c + 1 < NC) asm volatile("cp.async.wait_group 1;" ::: "memory");
        else            asm volatile("cp.async.wait_group 0;" ::: "memory");
        __syncthreads();
        if (c + 2 < NC) issue(c + 2);
        uint32_t st = sb + (uint32_t)(c % 3) * STAGE_BYTES;
        int lrow = l & 15, lcb = l >> 4;
#pragma unroll
        for (int k16 = 0; k16 < 4; k16++) {
            uint32_t coff = (uint32_t)((k16 * 16 + lcb * 8) * 2);
            uint32_t bh[4][4];
#pragma unroll
            for (int nt2 = 0; nt2 < 4; nt2++) {
                uint32_t roff = (uint32_t)((wn * 64 + nt2 * 16 + lrow) * (ASTR * 2));
                ldm4(bh[nt2], st + HALF_BYTES + roff + coff);
            }
#pragma unroll
            for (int mt = 0; mt < 2; mt++) {
                uint32_t roff = (uint32_t)((wm * 32 + mt * 16 + lrow) * (ASTR * 2));
                uint32_t ah[4];
                ldm4(ah, st + roff + coff);
#pragma unroll
                for (int nt = 0; nt < 8; nt++) {
                    int nt2 = nt >> 1, sel = nt & 1;
                    mma16816h(acc[mt][nt], ah, bh[nt2][sel], bh[nt2][sel + 2]);
                }
            }
        }
    }

#pragma unroll
    for (int mt = 0; mt < 2; mt++) {
#pragma unroll
        for (int nt = 0; nt < 8; nt++) {
            int row = m0 + wm * 32 + mt * 16 + (l >> 2);
            int col = n0 + wn * 64 + nt * 8 + 2 * (l & 3);
            if (col < N) {
                if (col >= auxcol) {
                    int ac = col - auxcol;
                    if (row < M) {
                        aux[row * 20 + ac]     = acc[mt][nt][0];
                        aux[row * 20 + ac + 1] = acc[mt][nt][1];
                    }
                    int row2 = row + 8;
                    if (row2 < M) {
                        aux[row2 * 20 + ac]     = acc[mt][nt][2];
                        aux[row2 * 20 + ac + 1] = acc[mt][nt][3];
                    }
                } else {
                    if (row < M)
                        *(__half2*)(C + (long)row * ldc + col) =
                            __floats2half2_rn(acc[mt][nt][0], acc[mt][nt][1]);
                    int row2 = row + 8;
                    if (row2 < M)
                        *(__half2*)(C + (long)row2 * ldc + col) =
                            __floats2half2_rn(acc[mt][nt][2], acc[mt][nt][3]);
                }
            }
        }
    }
}

// ---------------- latency-optimized skinny GEMM ----------------
__global__ void __launch_bounds__(256)
mlp8(const float* __restrict__ A, const float* __restrict__ W,
     float* __restrict__ C, const float* __restrict__ bias,
     int M, int N, int K, int lda, int ldc, int coff, int relu) {
    __shared__ float sact[8 * 1504];
    int t = threadIdx.x;
    int j = t & 63, kc = t >> 6;
    int jg = blockIdx.x * 64 + j;
    int r0 = blockIdx.y * 8;

    for (int i = t; i < 8 * K; i += 256) {
        int r = i / K, k = i - r * K;
        int row = r0 + r;
        sact[i] = (row < M) ? A[(long)row * lda + k] : 0.f;
    }
    __syncthreads();

    float acc[8];
#pragma unroll
    for (int r = 0; r < 8; r++) acc[r] = 0.f;
    if (jg < N) {
        for (int k = kc; k < K; k += 4) {
            float wv = W[(long)k * N + jg];
            const float* ar = &sact[k];
#pragma unroll
            for (int r = 0; r < 8; r++) acc[r] += ar[r * K] * wv;
        }
    }
    __syncthreads();
    float* red = sact;
#pragma unroll
    for (int r = 0; r < 8; r++) red[(j * 4 + kc) + r * 256] = acc[r];
    __syncthreads();
    if (kc == 0 && jg < N) {
        float b = bias ? bias[jg] : 0.f;
#pragma unroll
        for (int r = 0; r < 8; r++) {
            int row = r0 + r;
            if (row >= M) break;
            float v = red[j * 4 + r * 256] + red[j * 4 + 1 + r * 256]
                    + red[j * 4 + 2 + r * 256] + red[j * 4 + 3 + r * 256] + b;
            if (relu) v = fmaxf(v, 0.f);
            C[(long)row * ldc + coff + jg] = v;
        }
    }
}

// ---------------- CSR build ----------------
__global__ void k_count(const int* __restrict__ edge) {
    int i = blockIdx.x * blockDim.x + threadIdx.x;
    if (i >= ET) return;
    int dst = (i < EE) ? edge[EE + i] : i - EE;
    atomicAdd(&g_cnt[dst], 1);
}
__global__ void __launch_bounds__(256) k_scanA() {
    __shared__ int s[256];
    int t = threadIdx.x;
    int i = blockIdx.x * 256 + t;
    s[t] = (i < NN) ? g_cnt[i] : 0;
    __syncthreads();
    for (int off = 128; off > 0; off >>= 1) {
        if (t < off) s[t] += s[t + off];
        __syncthreads();
    }
    if (t == 0) g_bsum[blockIdx.x] = s[0];
}
__global__ void k_scanB() {
    __shared__ int s[NB];
    int t = threadIdx.x;
    if (t < NB) s[t] = g_bsum[t];
    __syncthreads();
    if (t == 0) {
        int r = 0;
        for (int i = 0; i < NB; i++) { int v = s[i]; g_bpre[i] = r; r += v; }
        g_off[NN] = r;
    }
}
__global__ void __launch_bounds__(256) k_scanC() {
    __shared__ int s[256];
    int t = threadIdx.x;
    int i = blockIdx.x * 256 + t;
    int c = (i < NN) ? g_cnt[i] : 0;
    s[t] = c;
    __syncthreads();
    for (int off = 1; off < 256; off <<= 1) {
        int v = (t >= off) ? s[t - off] : 0;
        __syncthreads();
        s[t] += v;
        __syncthreads();
    }
    if (i < NN) {
        g_off[i] = g_bpre[blockIdx.x] + s[t] - c;
        g_dinv[i] = rsqrtf((float)(c > 0 ? c : 1));
    }
}
__global__ void k_scatter(const int* __restrict__ edge) {
    int i = blockIdx.x * blockDim.x + threadIdx.x;
    if (i >= ET) return;
    int src = (i < EE) ? edge[i]      : i - EE;
    int dst = (i < EE) ? edge[EE + i] : i - EE;
    int old = atomicSub(&g_cnt[dst], 1);
    g_srcA[g_off[dst] + old - 1] = src;
}
__global__ void k_startB(const int* __restrict__ batch) {
    int n = blockIdx.x * blockDim.x + threadIdx.x;
    if (n >= NN) return;
    int b = batch[n];
    if (n == 0) {
        for (int bb = 0; bb <= b; bb++) g_start[bb] = 0;
    } else {
        int pb = batch[n - 1];
        if (pb != b) for (int bb = pb + 1; bb <= b; bb++) g_start[bb] = n;
    }
    if (n == NN - 1) {
        for (int bb = b + 1; bb <= BB; bb++) g_start[bb] = NN;
    }
}

// ---------------- fused softmax + GAT aggregation ----------------
__device__ __forceinline__ uint32_t fmapU(float f) {
    uint32_t u = __float_as_uint(f);
    return u ^ (uint32_t)(((int)u >> 31) | 0x80000000);
}
__device__ __forceinline__ float finvU(uint32_t u) {
    return (u & 0x80000000u) ? __uint_as_float(u ^ 0x80000000u) : __uint_as_float(~u);
}
__global__ void __launch_bounds__(256) k_gat_soft_agg(const float* __restrict__ gat_b) {
    __shared__ float sal[DMAX * HH];
    __shared__ int ssrc[DMAX];
    __shared__ uint32_t sm[HH];
    __shared__ float sden[HH], sad[HH];
    int n = blockIdx.x, t = threadIdx.x;
    int lo = g_off[n], d = g_off[n + 1] - lo;
    bool small = (d <= DMAX);
    float* ebuf = small ? sal : &g_e[(long)lo * HH];
    const int* sp = small ? ssrc : &g_srcA[lo];
    if (t < HH) { sm[t] = fmapU(-INFINITY); sden[t] = 0.f; sad[t] = g_asad[n * 20 + 10 + t]; }
    if (small)
        for (int i = t; i < d; i += 256) ssrc[i] = g_srcA[lo + i];
    __syncthreads();
    int tot = d * HH;
    for (int p = t; p < tot; p += 256) {
        int i = p / HH, h = p - i * HH;
        int src = sp[i];
        float e = g_asad[src * 20 + h] + sad[h];
        e = (e > 0.f) ? e : 0.2f * e;
        ebuf[p] = e;
        atomicMax(&sm[h], fmapU(e));
    }
    __syncthreads();
    for (int p = t; p < tot; p += 256) {
        int h = p % HH;
        float ex = expf(ebuf[p] - finvU(sm[h]));
        ebuf[p] = ex;
        atomicAdd(&sden[h], ex);
    }
    __syncthreads();
    if (t < HH) sden[t] = 1.f / sden[t];
    __syncthreads();

    if (t >= 208) return;
    long base = (long)n * KPG + t * 4;
    if (t >= 195) {
        __half2 z = __floats2half2_rn(0.f, 0.f);
        *(__half2*)(g_Ag + base) = z;
        *(__half2*)(g_Ag + base + 2) = z;
        return;
    }
    int q = t * 4;
    int h0 = q / FF, h1 = (q + 1) / FF, h2 = (q + 2) / FF, h3 = (q + 3) / FF;
    float ax = 0.f, ay = 0.f, az = 0.f, aw = 0.f;
    for (int idx = 0; idx < d; idx++) {
        int s = sp[idx];
        uint2 u = *(const uint2*)(g_hH + (long)s * NEXT + q);
        float2 v01 = __half22float2(*(__half2*)&u.x);
        float2 v23 = __half22float2(*(__half2*)&u.y);
        const float* al = &ebuf[idx * HH];
        ax += v01.x * al[h0]; ay += v01.y * al[h1]; az += v23.x * al[h2]; aw += v23.y * al[h3];
    }
    ax *= sden[h0]; ay *= sden[h1]; az *= sden[h2]; aw *= sden[h3];
    float v0 = fmaxf(ax + gat_b[q + 0], 0.f);
    float v1 = fmaxf(ay + gat_b[q + 1], 0.f);
    float v2 = fmaxf(az + gat_b[q + 2], 0.f);
    float v3 = fmaxf(aw + gat_b[q + 3], 0.f);
    *(__half2*)(g_Ag + base)     = __floats2half2_rn(v0, v1);
    *(__half2*)(g_Ag + base + 2) = __floats2half2_rn(v2, v3);
}

// ---------------- GCN aggregation ----------------
__global__ void __launch_bounds__(256) k_gcn_agg(const float* __restrict__ gcn_b) {
    int n = blockIdx.x, t = threadIdx.x;
    if (t >= 195) return;
    int q = t * 4;
    float dn = g_dinv[n];
    float ax = 0.f, ay = 0.f, az = 0.f, aw = 0.f;
    int lo = g_off[n], hi = g_off[n + 1];
    for (int idx = lo; idx < hi; idx++) {
        int s = g_srcA[idx];
        float norm = dn * g_dinv[s];
        uint2 u = *(const uint2*)(g_h2H + (long)s * HID + q);
        float2 v01 = __half22float2(*(__half2*)&u.x);
        float2 v23 = __half22float2(*(__half2*)&u.y);
        ax += v01.x * norm; ay += v01.y * norm; az += v23.x * norm; aw += v23.y * norm;
    }
    float v0 = fmaxf(ax + gcn_b[q + 0], 0.f);
    float v1 = fmaxf(ay + gcn_b[q + 1], 0.f);
    float v2 = fmaxf(az + gcn_b[q + 2], 0.f);
    float v3 = fmaxf(aw + gcn_b[q + 3], 0.f);
    *(__half2*)(g_x2H + (long)n * HID + q)     = __floats2half2_rn(v0, v1);
    *(__half2*)(g_x2H + (long)n * HID + q + 2) = __floats2half2_rn(v2, v3);
}

// ---------------- segment pool ----------------
__global__ void __launch_bounds__(256) k_pool() {
    int b = blockIdx.x, t = threadIdx.x;
    if (t >= 195) return;
    int q = t * 4;
    int lo = g_start[b], hi = g_start[b + 1];
    float ax = 0.f, ay = 0.f, az = 0.f, aw = 0.f;
    for (int n = lo; n < hi; n++) {
        uint2 u = *(const uint2*)(g_x2H + (long)n * HID + q);
        float2 v01 = __half22float2(*(__half2*)&u.x);
        float2 v23 = __half22float2(*(__half2*)&u.y);
        ax += v01.x; ay += v01.y; az += v23.x; aw += v23.y;
    }
    float* o = g_xg + (long)b * HID + q;
    o[0] = ax; o[1] = ay; o[2] = az; o[3] = aw;
}

// ---------------- protein branch ----------------
__global__ void k_Pbias(const float* __restrict__ emb, const float* __restrict__ cW,
                        const float* __restrict__ fxtW, const float* __restrict__ cb) {
    int bi = blockIdx.x, j = threadIdx.x;
    if (bi < 256) {
        int o = bi >> 3, c = bi & 7;
        int t0 = c * 125, t1 = min(t0 + 125, COUT);
        float p = 0.f;
        for (int t = t0; t < t1; t++)
            p += fxtW[((long)(o * COUT + t)) * 128 + j];
        atomicAdd(&g_biasY[j], cb[o] * p);
    } else {
        int g = (bi - 256) * 128 + j;
        if (g >= VOC * NF * KS) return;
        int v = g / (NF * KS), r = g % (NF * KS);
        int o = r / KS, k = r % KS;
        float s = 0.f;
#pragma unroll 16
        for (int e = 0; e < EMB; e++)
            s += emb[v * EMB + e] * cW[o * EMB * KS + e * KS + k];
        g_P[g] = s;
    }
}
__global__ void k_R(const float* __restrict__ fxtW) {
    __shared__ float Ps[VOC * NF * KS];
    int s = blockIdx.x, j = threadIdx.x;
    for (int idx = j; idx < VOC * NF * KS; idx += 128) Ps[idx] = g_P[idx];
    __syncthreads();
    float acc[VOC];
#pragma unroll
    for (int v = 0; v < VOC; v++) acc[v] = 0.f;
    int kmin = (s > COUT - 1) ? (s - (COUT - 1)) : 0;
    int kmax = (s < KS - 1) ? s : (KS - 1);
    for (int o = 0; o < NF; o++) {
        for (int k = kmin; k <= kmax; k++) {
            float w = fxtW[((long)(o * COUT + s - k)) * 128 + j];
#pragma unroll
            for (int v = 0; v < VOC; v++)
                acc[v] += Ps[v * (NF * KS) + o * KS + k] * w;
        }
    }
#pragma unroll
    for (int v = 0; v < VOC; v++)
        g_R[((long)v * SEQ + s) * 128 + j] = acc[v];
}
__global__ void k_Y(const int* __restrict__ target, const float* __restrict__ fxt_b) {
    __shared__ int sv[SEQ];
    int b = blockIdx.x, j = threadIdx.x;
    for (int i = j; i < SEQ; i += 128) sv[i] = target[b * SEQ + i];
    __syncthreads();
    float acc = g_biasY[j] + fxt_b[j];
    for (int s = 0; s < SEQ; s += 4) {
        float r0 = g_R[((long)sv[s]     * SEQ + s)     * 128 + j];
        float r1 = g_R[((long)sv[s + 1] * SEQ + s + 1) * 128 + j];
        float r2 = g_R[((long)sv[s + 2] * SEQ + s + 2) * 128 + j];
        float r3 = g_R[((long)sv[s + 3] * SEQ + s + 3) * 128 + j];
        acc += (r0 + r1) + (r2 + r3);
    }
    g_xc[b * 256 + 128 + j] = acc;
}

// ---------------- output ----------------
__global__ void k_out(const float* __restrict__ oW, const float* __restrict__ ob,
                      float* __restrict__ out) {
    __shared__ float red[4];
    int b = blockIdx.x, j = threadIdx.x;
    float v = g_t5[b * 128 + j] * oW[j];
#pragma unroll
    for (int off = 16; off; off >>= 1) v += __shfl_down_sync(0xffffffffu, v, off);
    if ((j & 31) == 0) red[j >> 5] = v;
    __syncthreads();
    if (j == 0) out[b] = red[0] + red[1] + red[2] + red[3] + ob[0];
}

// ---------------- host ----------------
static inline dim3 ggrid(long n, int t) { return dim3((unsigned)((n + t - 1) / t)); }

extern "C" void kernel_launch(void* const* d_in, const int* in_sizes, int n_in,
                              void* d_out, int out_size) {
    const float* x      = (const float*)d_in[0];
    const int*   edge   = (const int*)  d_in[1];
    const int*   batch  = (const int*)  d_in[2];
    const int*   target = (const int*)  d_in[3];
    const float* gat_W  = (const float*)d_in[4];
    const float* a_src  = (const float*)d_in[5];
    const float* a_dst  = (const float*)d_in[6];
    const float* gat_b  = (const float*)d_in[7];
    const float* gcn_W  = (const float*)d_in[8];
    const float* gcn_b  = (const float*)d_in[9];
    const float* fcg1_W = (const float*)d_in[10];
    const float* fcg1_b = (const float*)d_in[11];
    const float* fcg2_W = (const float*)d_in[12];
    const float* fcg2_b = (const float*)d_in[13];
    const float* emb    = (const float*)d_in[14];
    const float* cW     = (const float*)d_in[15];
    const float* cb     = (const float*)d_in[16];
    const float* fxt_W  = (const float*)d_in[17];
    const float* fxt_b  = (const float*)d_in[18];
    const float* f1_W   = (const float*)d_in[19];
    const float* f1_b   = (const float*)d_in[20];
    const float* f2_W   = (const float*)d_in[21];
    const float* f2_b   = (const float*)d_in[22];
    const float* f3_W   = (const float*)d_in[23];
    const float* f3_b   = (const float*)d_in[24];
    const float* f4_W   = (const float*)d_in[25];
    const float* f4_b   = (const float*)d_in[26];
    const float* o_W    = (const float*)d_in[27];
    const float* o_b    = (const float*)d_in[28];
    float* out = (float*)d_out;

    float *p_xg, *p_t1, *p_xc, *p_t2, *p_t3, *p_t4, *p_t5, *p_asad;
    __half *p_hH, *p_h2H, *p_Axh, *p_Bah, *p_Ag, *p_Bgh;
    cudaGetSymbolAddress((void**)&p_hH,  g_hH);
    cudaGetSymbolAddress((void**)&p_h2H, g_h2H);
    cudaGetSymbolAddress((void**)&p_asad, g_asad);
    cudaGetSymbolAddress((void**)&p_xg,  g_xg);
    cudaGetSymbolAddress((void**)&p_t1,  g_t1);
    cudaGetSymbolAddress((void**)&p_xc,  g_xc);
    cudaGetSymbolAddress((void**)&p_t2,  g_t2);
    cudaGetSymbolAddress((void**)&p_t3,  g_t3);
    cudaGetSymbolAddress((void**)&p_t4,  g_t4);
    cudaGetSymbolAddress((void**)&p_t5,  g_t5);
    cudaGetSymbolAddress((void**)&p_Axh, g_Axh);
    cudaGetSymbolAddress((void**)&p_Bah, g_Bah);
    cudaGetSymbolAddress((void**)&p_Ag,  g_Ag);
    cudaGetSymbolAddress((void**)&p_Bgh, g_Bgh);

    static cudaStream_t s1, s2;
    static cudaEvent_t eF, e1, e2, eW;
    static int inited = 0;
    if (!inited) {
        cudaStreamCreateWithFlags(&s1, cudaStreamNonBlocking);
        cudaStreamCreateWithFlags(&s2, cudaStreamNonBlocking);
        cudaEventCreateWithFlags(&eF, cudaEventDisableTiming);
        cudaEventCreateWithFlags(&e1, cudaEventDisableTiming);
        cudaEventCreateWithFlags(&e2, cudaEventDisableTiming);
        cudaEventCreateWithFlags(&eW, cudaEventDisableTiming);
        cudaFuncSetAttribute(gemm_mma, cudaFuncAttributeMaxDynamicSharedMemorySize, GEMM_SMEM);
        inited = 1;
    }

    cudaEventRecord(eF, 0);
    cudaStreamWaitEvent(s1, eF, 0);
    cudaStreamWaitEvent(s2, eF, 0);

    // main: GAT conversions + attn rows (critical-path prologue only)
    k_transW<<<dim3(4, 25), 256>>>(gat_W, p_Bah, FF, HID, KPA);
    k_prep<<<PB_A + PB_E, 256>>>(x, gat_W, a_src, a_dst);
    // s2: GCN weight transpose (needed only at GCN GEMM) + protein branch
    k_transW<<<dim3(26, 25), 256, 0, s2>>>(gcn_W, p_Bgh, HID, HID, KPG);
    cudaEventRecord(eW, s2);
    k_init0<<<1, 128, 0, s2>>>();
    k_Pbias<<<308, 128, 0, s2>>>(emb, cW, fxt_W, cb);
    k_R<<<SEQ, 128, 0, s2>>>(fxt_W);
    k_Y<<<BB, 128, 0, s2>>>(target, fxt_b);
    cudaEventRecord(e2, s2);
    // s1: CSR build
    k_count<<<ggrid(ET, 256), 256, 0, s1>>>(edge);
    k_startB<<<ggrid(NN, 256), 256, 0, s1>>>(batch);
    k_scanA<<<NB, 256, 0, s1>>>();
    k_scanB<<<1, 128, 0, s1>>>();
    k_scanC<<<NB, 256, 0, s1>>>();
    // main: GAT GEMM
    gemm_mma<<<dim3(7, 157), 256, GEMM_SMEM>>>(p_Axh, p_Bah, p_hH, NN, NEXT, KPA, KPA / KC, NEXT,
                                               p_asad, HID);
    // s1: scatter
    k_scatter<<<ggrid(ET, 256), 256, 0, s1>>>(edge);
    cudaEventRecord(e1, s1);
    // main: graph branch
    cudaStreamWaitEvent(0, e1, 0);
    k_gat_soft_agg<<<NN, 256>>>(gat_b);
    cudaStreamWaitEvent(0, eW, 0);
    gemm_mma<<<dim3(7, 157), 256, GEMM_SMEM>>>(p_Ag, p_Bgh, p_h2H, NN, HID, KPG, KPG / KC, HID,
                                               nullptr, 1 << 30);
    k_gcn_agg<<<NN, 256>>>(gcn_b);
    k_pool<<<BB, 256>>>();
    // head
    mlp8<<<dim3(24, 25), 256>>>(p_xg, fcg1_W, p_t1, fcg1_b, BB, 1500, HID, HID, 1500, 0, 1);
    mlp8<<<dim3(2, 25), 256>>>(p_t1, fcg2_W, p_xc, fcg2_b, BB, 128, 1500, 1500, 256, 0, 0);
    cudaStreamWaitEvent(0, e2, 0);
    mlp8<<<dim3(16, 25), 256>>>(p_xc, f1_W, p_t2, f1_b, BB, 1024, 256, 256, 1024, 0, 1);
    mlp8<<<dim3(8, 25), 256>>>(p_t2, f2_W, p_t3, f2_b, BB, 512, 1024, 1024, 512, 0, 1);
    mlp8<<<dim3(4, 25), 256>>>(p_t3, f3_W, p_t4, f3_b, BB, 256, 512, 512, 256, 0, 1);
    mlp8<<<dim3(2, 25), 256>>>(p_t4, f4_W, p_t5, f4_b, BB, 128, 256, 256, 128, 0, 1);
    k_out<<<BB, 128>>>(o_W, o_b, out);
}

// round 15
// speedup vs baseline: 1.0322x; 1.0159x over previous
#include <cuda_runtime.h>
#include <cuda_fp16.h>
#include <math.h>
#include <stdint.h>

#define NN   20000
#define EE   400000
#define ET   (EE + NN)
#define HH   10
#define FF   78
#define HID  780
#define NEXT 800
#define BB   200
#define SEQ  1000
#define VOC  26
#define EMB  128
#define NF   32
#define KS   8
#define COUT 993
#define KPA  128
#define KPG  832
#define DMAX 256
#define NB   79

// ---------------- scratch ----------------
__device__ __half g_hH [(long)NN * NEXT];
__device__ __half g_h2H[(long)NN * HID];
__device__ __half g_x2H[(long)NN * HID];
__device__ float g_asad[NN * 20];
__device__ float g_e  [(long)ET * HH];
__device__ float g_xg [BB * HID];
__device__ float g_t1 [BB * 1500];
__device__ float g_xc [BB * 256];
__device__ float g_t2 [BB * 1024];
__device__ float g_t3 [BB * 512];
__device__ float g_t4 [BB * 256];
__device__ float g_P  [VOC * NF * KS];
__device__ float g_R  [(long)VOC * SEQ * 128];
__device__ float g_biasY[128];
__device__ int   g_cnt[NN];        // invariant: zero at kernel_launch entry
__device__ int   g_off[NN + 1];
__device__ int   g_bsum[NB];
__device__ int   g_bpre[NB];
__device__ int   g_srcA[ET];
__device__ int   g_start[BB + 1];
__device__ float g_dinv[NN];
__device__ __half g_Axh[(long)NN * KPA];
__device__ __half g_Bah[(long)NEXT * KPA];
__device__ __half g_Ag [(long)NN * KPG];
__device__ __half g_Bgh[(long)HID * KPG];

// ---------------- helpers ----------------
__device__ __forceinline__ uint32_t smem_u32(const void* p) {
    uint32_t a;
    asm("{ .reg .u64 t; cvta.to.shared.u64 t, %1; cvt.u32.u64 %0, t; }" : "=r"(a) : "l"(p));
    return a;
}
__device__ __forceinline__ void cpasync16(uint32_t dst, const void* src, int nbytes) {
    asm volatile("cp.async.cg.shared.global [%0], [%1], 16, %2;"
                 :: "r"(dst), "l"(__cvta_generic_to_global(src)), "r"(nbytes) : "memory");
}
__device__ __forceinline__ void ldm4(uint32_t* r, uint32_t addr) {
    asm volatile("ldmatrix.sync.aligned.m8n8.x4.shared.b16 {%0,%1,%2,%3}, [%4];"
                 : "=r"(r[0]), "=r"(r[1]), "=r"(r[2]), "=r"(r[3]) : "r"(addr));
}
__device__ __forceinline__ void mma16816h(float* c, const uint32_t* a, uint32_t b0, uint32_t b1) {
    asm volatile("mma.sync.aligned.m16n8k16.row.col.f32.f16.f16.f32 "
                 "{%0,%1,%2,%3}, {%4,%5,%6,%7}, {%8,%9}, {%0,%1,%2,%3};"
                 : "+f"(c[0]), "+f"(c[1]), "+f"(c[2]), "+f"(c[3])
                 : "r"(a[0]), "r"(a[1]), "r"(a[2]), "r"(a[3]), "r"(b0), "r"(b1));
}

// ---------------- tiny init ----------------
__global__ void k_init0() {
    g_biasY[threadIdx.x] = 0.f;
}

// ---------------- prep ----------------
#define PB_A 10000
#define PB_E 20
__global__ void __launch_bounds__(256) k_prep(const float* __restrict__ x,
                                              const float* __restrict__ gat_W,
                                              const float* __restrict__ aS,
                                              const float* __restrict__ aD) {
    int bid = blockIdx.x, t = threadIdx.x;
    if (bid < PB_A) {
        int i = bid * 256 + t;
        int m = i >> 7, k = i & 127;
        g_Axh[i] = __float2half_rn(k < FF ? x[(long)m * FF + k] : 0.f);
    } else {
        int i = bid - PB_A;
        int k = t;
        if (k >= 128) return;
        int h = i % 10;
        const float* av = ((i < 10) ? aS : aD) + h * FF;
        float s = 0.f;
        if (k < FF) {
            const float* wr = gat_W + (long)k * HID + h * FF;
#pragma unroll 13
            for (int f = 0; f < FF; f++) s += wr[f] * av[f];
        }
        g_Bah[(long)(HID + i) * KPA + k] = __float2half_rn(s);
    }
}

// ---------------- coalesced transpose-convert ----------------
__global__ void __launch_bounds__(256) k_transW(const float* __restrict__ W,
                                                __half* __restrict__ dst,
                                                int K, int N, int Kp) {
    __shared__ float tile[32][33];
    int k0 = blockIdx.x * 32, n0 = blockIdx.y * 32;
    int tx = threadIdx.x & 31, ty = threadIdx.x >> 5;
#pragma unroll
    for (int r = 0; r < 4; r++) {
        int k = k0 + ty + r * 8, n = n0 + tx;
        tile[ty + r * 8][tx] = (k < K && n < N) ? W[(long)k * N + n] : 0.f;
    }
    __syncthreads();
#pragma unroll
    for (int r = 0; r < 4; r++) {
        int n = n0 + ty + r * 8, k = k0 + tx;
        if (n < N && k < Kp)
            dst[(long)n * Kp + k] = __float2half_rn(tile[tx][ty + r * 8]);
    }
}

// ============ fp16 tensor-core GEMM, KC=64, 3-stage cp.async pipeline ============
#define KC 64
#define ASTR 72
#define HALF_BYTES (128 * ASTR * 2)
#define STAGE_BYTES (2 * HALF_BYTES)
#define GEMM_SMEM (3 * STAGE_BYTES)

__global__ void __launch_bounds__(256)
gemm_mma(const __half* __restrict__ Ah, const __half* __restrict__ Bh,
         __half* __restrict__ C, int M, int N, int Kp, int NC, int ldc,
         float* __restrict__ aux, int auxcol) {
    extern __shared__ char smem_raw[];
    uint32_t sb = smem_u32(smem_raw);
    int tid = threadIdx.x, w = tid >> 5, l = tid & 31;
    int m0 = blockIdx.y * 128, n0 = blockIdx.x * 128;
    int wm = w & 3, wn = w >> 2;

    float acc[2][8][4];
#pragma unroll
    for (int i = 0; i < 2; i++)
#pragma unroll
        for (int j = 0; j < 8; j++)
#pragma unroll
            for (int q = 0; q < 4; q++) acc[i][j][q] = 0.f;

    auto issue = [&](int c) {
        int k0 = c * KC;
        uint32_t st = sb + (uint32_t)(c % 3) * STAGE_BYTES;
#pragma unroll
        for (int p = 0; p < 4; p++) {
            int f = tid + p * 256;
            int row = f >> 3, c16 = f & 7;
            uint32_t doff = (uint32_t)(row * (ASTR * 2) + c16 * 16);
            int am = m0 + row;
            int amc = am < M ? am : M - 1;
            int av = am < M ? 16 : 0;
            cpasync16(st + doff, Ah + (long)amc * Kp + k0 + c16 * 8, av);
            int bn = n0 + row;
            int bnc = bn < N ? bn : N - 1;
            int bv = bn < N ? 16 : 0;
            cpasync16(st + HALF_BYTES + doff, Bh + (long)bnc * Kp + k0 + c16 * 8, bv);
        }
        asm volatile("cp.async.commit_group;" ::: "memory");
    };

    issue(0);
    if (NC > 1) issue(1);
    for (int c = 0; c < NC; c++) {
        if (c + 1 < NC) asm volatile("cp.async.wait_group 1;" ::: "memory");
        else            asm volatile("cp.async.wait_group 0;" ::: "memory");
        __syncthreads();
        if (c + 2 < NC) issue(c + 2);
        uint32_t st = sb + (uint32_t)(c % 3) * STAGE_BYTES;
        int lrow = l & 15, lcb = l >> 4;
#pragma unroll
        for (int k16 = 0; k16 < 4; k16++) {
            uint32_t coff = (uint32_t)((k16 * 16 + lcb * 8) * 2);
            uint32_t bh[4][4];
#pragma unroll
            for (int nt2 = 0; nt2 < 4; nt2++) {
                uint32_t roff = (uint32_t)((wn * 64 + nt2 * 16 + lrow) * (ASTR * 2));
                ldm4(bh[nt2], st + HALF_BYTES + roff + coff);
            }
#pragma unroll
            for (int mt = 0; mt < 2; mt++) {
                uint32_t roff = (uint32_t)((wm * 32 + mt * 16 + lrow) * (ASTR * 2));
                uint32_t ah[4];
                ldm4(ah, st + roff + coff);
#pragma unroll
                for (int nt = 0; nt < 8; nt++) {
                    int nt2 = nt >> 1, sel = nt & 1;
                    mma16816h(acc[mt][nt], ah, bh[nt2][sel], bh[nt2][sel + 2]);
                }
            }
        }
    }

#pragma unroll
    for (int mt = 0; mt < 2; mt++) {
#pragma unroll
        for (int nt = 0; nt < 8; nt++) {
            int row = m0 + wm * 32 + mt * 16 + (l >> 2);
            int col = n0 + wn * 64 + nt * 8 + 2 * (l & 3);
            if (col < N) {
                if (col >= auxcol) {
                    int ac = col - auxcol;
                    if (row < M) {
                        aux[row * 20 + ac]     = acc[mt][nt][0];
                        aux[row * 20 + ac + 1] = acc[mt][nt][1];
                    }
                    int row2 = row + 8;
                    if (row2 < M) {
                        aux[row2 * 20 + ac]     = acc[mt][nt][2];
                        aux[row2 * 20 + ac + 1] = acc[mt][nt][3];
                    }
                } else {
                    if (row < M)
                        *(__half2*)(C + (long)row * ldc + col) =
                            __floats2half2_rn(acc[mt][nt][0], acc[mt][nt][1]);
                    int row2 = row + 8;
                    if (row2 < M)
                        *(__half2*)(C + (long)row2 * ldc + col) =
                            __floats2half2_rn(acc[mt][nt][2], acc[mt][nt][3]);
                }
            }
        }
    }
}

// ---------------- latency-optimized skinny GEMM ----------------
__global__ void __launch_bounds__(256)
mlp8(const float* __restrict__ A, const float* __restrict__ W,
     float* __restrict__ C, const float* __restrict__ bias,
     int M, int N, int K, int lda, int ldc, int coff, int relu) {
    __shared__ float sact[8 * 1504];
    int t = threadIdx.x;
    int j = t & 63, kc = t >> 6;
    int jg = blockIdx.x * 64 + j;
    int r0 = blockIdx.y * 8;

    for (int i = t; i < 8 * K; i += 256) {
        int r = i / K, k = i - r * K;
        int row = r0 + r;
        sact[i] = (row < M) ? A[(long)row * lda + k] : 0.f;
    }
    __syncthreads();

    float acc[8];
#pragma unroll
    for (int r = 0; r < 8; r++) acc[r] = 0.f;
    if (jg < N) {
        for (int k = kc; k < K; k += 4) {
            float wv = W[(long)k * N + jg];
            const float* ar = &sact[k];
#pragma unroll
            for (int r = 0; r < 8; r++) acc[r] += ar[r * K] * wv;
        }
    }
    __syncthreads();
    float* red = sact;
#pragma unroll
    for (int r = 0; r < 8; r++) red[(j * 4 + kc) + r * 256] = acc[r];
    __syncthreads();
    if (kc == 0 && jg < N) {
        float b = bias ? bias[jg] : 0.f;
#pragma unroll
        for (int r = 0; r < 8; r++) {
            int row = r0 + r;
            if (row >= M) break;
            float v = red[j * 4 + r * 256] + red[j * 4 + 1 + r * 256]
                    + red[j * 4 + 2 + r * 256] + red[j * 4 + 3 + r * 256] + b;
            if (relu) v = fmaxf(v, 0.f);
            C[(long)row * ldc + coff + jg] = v;
        }
    }
}

// ---------------- CSR build ----------------
__global__ void k_count(const int* __restrict__ edge) {
    int i = blockIdx.x * blockDim.x + threadIdx.x;
    if (i >= ET) return;
    int dst = (i < EE) ? edge[EE + i] : i - EE;
    atomicAdd(&g_cnt[dst], 1);
}
__global__ void __launch_bounds__(256) k_scanA() {
    __shared__ int s[256];
    int t = threadIdx.x;
    int i = blockIdx.x * 256 + t;
    s[t] = (i < NN) ? g_cnt[i] : 0;
    __syncthreads();
    for (int off = 128; off > 0; off >>= 1) {
        if (t < off) s[t] += s[t + off];
        __syncthreads();
    }
    if (t == 0) g_bsum[blockIdx.x] = s[0];
}
__global__ void k_scanB() {
    __shared__ int s[NB];
    int t = threadIdx.x;
    if (t < NB) s[t] = g_bsum[t];
    __syncthreads();
    if (t == 0) {
        int r = 0;
        for (int i = 0; i < NB; i++) { int v = s[i]; g_bpre[i] = r; r += v; }
        g_off[NN] = r;
    }
}
__global__ void __launch_bounds__(256) k_scanC() {
    __shared__ int s[256];
    int t = threadIdx.x;
    int i = blockIdx.x * 256 + t;
    int c = (i < NN) ? g_cnt[i] : 0;
    s[t] = c;
    __syncthreads();
    for (int off = 1; off < 256; off <<= 1) {
        int v = (t >= off) ? s[t - off] : 0;
        __syncthreads();
        s[t] += v;
        __syncthreads();
    }
    if (i < NN) {
        g_off[i] = g_bpre[blockIdx.x] + s[t] - c;
        g_dinv[i] = rsqrtf((float)(c > 0 ? c : 1));
    }
}
__global__ void k_scatter(const int* __restrict__ edge) {
    int i = blockIdx.x * blockDim.x + threadIdx.x;
    if (i >= ET) return;
    int src = (i < EE) ? edge[i]      : i - EE;
    int dst = (i < EE) ? edge[EE + i] : i - EE;
    int old = atomicSub(&g_cnt[dst], 1);
    g_srcA[g_off[dst] + old - 1] = src;
}
__global__ void k_startB(const int* __restrict__ batch) {
    int n = blockIdx.x * blockDim.x + threadIdx.x;
    if (n >= NN) return;
    int b = batch[n];
    if (n == 0) {
        for (int bb = 0; bb <= b; bb++) g_start[bb] = 0;
    } else {
        int pb = batch[n - 1];
        if (pb != b) for (int bb = pb + 1; bb <= b; bb++) g_start[bb] = n;
    }
    if (n == NN - 1) {
        for (int bb = b + 1; bb <= BB; bb++) g_start[bb] = NN;
    }
}

// ---------------- fused softmax + GAT aggregation ----------------
__device__ __forceinline__ uint32_t fmapU(float f) {
    uint32_t u = __float_as_uint(f);
    return u ^ (uint32_t)(((int)u >> 31) | 0x80000000);
}
__device__ __forceinline__ float finvU(uint32_t u) {
    return (u & 0x80000000u) ? __uint_as_float(u ^ 0x80000000u) : __uint_as_float(~u);
}
__global__ void __launch_bounds__(256) k_gat_soft_agg(const float* __restrict__ gat_b) {
    __shared__ float sal[DMAX * HH];
    __shared__ int ssrc[DMAX];
    __shared__ uint32_t sm[HH];
    __shared__ float sden[HH], sad[HH];
    int n = blockIdx.x, t = threadIdx.x;
    int lo = g_off[n], d = g_off[n + 1] - lo;
    bool small = (d <= DMAX);
    float* ebuf = small ? sal : &g_e[(long)lo * HH];
    const int* sp = small ? ssrc : &g_srcA[lo];
    if (t < HH) { sm[t] = fmapU(-INFINITY); sden[t] = 0.f; sad[t] = g_asad[n * 20 + 10 + t]; }
    if (small)
        for (int i = t; i < d; i += 256) ssrc[i] = g_srcA[lo + i];
    __syncthreads();
    int tot = d * HH;
    for (int p = t; p < tot; p += 256) {
        int i = p / HH, h = p - i * HH;
        int src = sp[i];
        float e = g_asad[src * 20 + h] + sad[h];
        e = (e > 0.f) ? e : 0.2f * e;
        ebuf[p] = e;
        atomicMax(&sm[h], fmapU(e));
    }
    __syncthreads();
    for (int p = t; p < tot; p += 256) {
        int h = p % HH;
        float ex = expf(ebuf[p] - finvU(sm[h]));
        ebuf[p] = ex;
        atomicAdd(&sden[h], ex);
    }
    __syncthreads();
    if (t < HH) sden[t] = 1.f / sden[t];
    __syncthreads();

    if (t >= 208) return;
    long base = (long)n * KPG + t * 4;
    if (t >= 195) {
        __half2 z = __floats2half2_rn(0.f, 0.f);
        *(__half2*)(g_Ag + base) = z;
        *(__half2*)(g_Ag + base + 2) = z;
        return;
    }
    int q = t * 4;
    int h0 = q / FF, h1 = (q + 1) / FF, h2 = (q + 2) / FF, h3 = (q + 3) / FF;
    float ax = 0.f, ay = 0.f, az = 0.f, aw = 0.f;
    for (int idx = 0; idx < d; idx++) {
        int s = sp[idx];
        uint2 u = *(const uint2*)(g_hH + (long)s * NEXT + q);
        float2 v01 = __half22float2(*(__half2*)&u.x);
        float2 v23 = __half22float2(*(__half2*)&u.y);
        const float* al = &ebuf[idx * HH];
        ax += v01.x * al[h0]; ay += v01.y * al[h1]; az += v23.x * al[h2]; aw += v23.y * al[h3];
    }
    ax *= sden[h0]; ay *= sden[h1]; az *= sden[h2]; aw *= sden[h3];
    float v0 = fmaxf(ax + gat_b[q + 0], 0.f);
    float v1 = fmaxf(ay + gat_b[q + 1], 0.f);
    float v2 = fmaxf(az + gat_b[q + 2], 0.f);
    float v3 = fmaxf(aw + gat_b[q + 3], 0.f);
    *(__half2*)(g_Ag + base)     = __floats2half2_rn(v0, v1);
    *(__half2*)(g_Ag + base + 2) = __floats2half2_rn(v2, v3);
}

// ---------------- GCN aggregation ----------------
__global__ void __launch_bounds__(256) k_gcn_agg(const float* __restrict__ gcn_b) {
    int n = blockIdx.x, t = threadIdx.x;
    if (t >= 195) return;
    int q = t * 4;
    float dn = g_dinv[n];
    float ax = 0.f, ay = 0.f, az = 0.f, aw = 0.f;
    int lo = g_off[n], hi = g_off[n + 1];
    for (int idx = lo; idx < hi; idx++) {
        int s = g_srcA[idx];
        float norm = dn * g_dinv[s];
        uint2 u = *(const uint2*)(g_h2H + (long)s * HID + q);
        float2 v01 = __half22float2(*(__half2*)&u.x);
        float2 v23 = __half22float2(*(__half2*)&u.y);
        ax += v01.x * norm; ay += v01.y * norm; az += v23.x * norm; aw += v23.y * norm;
    }
    float v0 = fmaxf(ax + gcn_b[q + 0], 0.f);
    float v1 = fmaxf(ay + gcn_b[q + 1], 0.f);
    float v2 = fmaxf(az + gcn_b[q + 2], 0.f);
    float v3 = fmaxf(aw + gcn_b[q + 3], 0.f);
    *(__half2*)(g_x2H + (long)n * HID + q)     = __floats2half2_rn(v0, v1);
    *(__half2*)(g_x2H + (long)n * HID + q + 2) = __floats2half2_rn(v2, v3);
}

// ---------------- segment pool ----------------
__global__ void __launch_bounds__(256) k_pool() {
    int b = blockIdx.x, t = threadIdx.x;
    if (t >= 195) return;
    int q = t * 4;
    int lo = g_start[b], hi = g_start[b + 1];
    float ax = 0.f, ay = 0.f, az = 0.f, aw = 0.f;
    for (int n = lo; n < hi; n++) {
        uint2 u = *(const uint2*)(g_x2H + (long)n * HID + q);
        float2 v01 = __half22float2(*(__half2*)&u.x);
        float2 v23 = __half22float2(*(__half2*)&u.y);
        ax += v01.x; ay += v01.y; az += v23.x; aw += v23.y;
    }
    float* o = g_xg + (long)b * HID + q;
    o[0] = ax; o[1] = ay; o[2] = az; o[3] = aw;
}

// ---------------- protein branch ----------------
__global__ void k_Pbias(const float* __restrict__ emb, const float* __restrict__ cW,
                        const float* __restrict__ fxtW, const float* __restrict__ cb) {
    int bi = blockIdx.x, j = threadIdx.x;
    if (bi < 256) {
        int o = bi >> 3, c = bi & 7;
        int t0 = c * 125, t1 = min(t0 + 125, COUT);
        float p = 0.f;
        for (int t = t0; t < t1; t++)
            p += fxtW[((long)(o * COUT + t)) * 128 + j];
        atomicAdd(&g_biasY[j], cb[o] * p);
    } else {
        int g = (bi - 256) * 128 + j;
        if (g >= VOC * NF * KS) return;
        int v = g / (NF * KS), r = g % (NF * KS);
        int o = r / KS, k = r % KS;
        float s = 0.f;
#pragma unroll 16
        for (int e = 0; e < EMB; e++)
            s += emb[v * EMB + e] * cW[o * EMB * KS + e * KS + k];
        g_P[g] = s;
    }
}
__global__ void k_R(const float* __restrict__ fxtW) {
    __shared__ float Ps[VOC * NF * KS];
    int s = blockIdx.x, j = threadIdx.x;
    for (int idx = j; idx < VOC * NF * KS; idx += 128) Ps[idx] = g_P[idx];
    __syncthreads();
    float acc[VOC];
#pragma unroll
    for (int v = 0; v < VOC; v++) acc[v] = 0.f;
    int kmin = (s > COUT - 1) ? (s - (COUT - 1)) : 0;
    int kmax = (s < KS - 1) ? s : (KS - 1);
    for (int o = 0; o < NF; o++) {
        for (int k = kmin; k <= kmax; k++) {
            float w = fxtW[((long)(o * COUT + s - k)) * 128 + j];
#pragma unroll
            for (int v = 0; v < VOC; v++)
                acc[v] += Ps[v * (NF * KS) + o * KS + k] * w;
        }
    }
#pragma unroll
    for (int v = 0; v < VOC; v++)
        g_R[((long)v * SEQ + s) * 128 + j] = acc[v];
}
__global__ void k_Y(const int* __restrict__ target, const float* __restrict__ fxt_b) {
    __shared__ int sv[SEQ];
    int b = blockIdx.x, j = threadIdx.x;
    for (int i = j; i < SEQ; i += 128) sv[i] = target[b * SEQ + i];
    __syncthreads();
    float acc = g_biasY[j] + fxt_b[j];
    for (int s = 0; s < SEQ; s += 4) {
        float r0 = g_R[((long)sv[s]     * SEQ + s)     * 128 + j];
        float r1 = g_R[((long)sv[s + 1] * SEQ + s + 1) * 128 + j];
        float r2 = g_R[((long)sv[s + 2] * SEQ + s + 2) * 128 + j];
        float r3 = g_R[((long)sv[s + 3] * SEQ + s + 3) * 128 + j];
        acc += (r0 + r1) + (r2 + r3);
    }
    g_xc[b * 256 + 128 + j] = acc;
}

// ---------------- fused f4 layer + output dot ----------------
__global__ void __launch_bounds__(128) k_out2(const float* __restrict__ W4,
                                              const float* __restrict__ b4,
                                              const float* __restrict__ oW,
                                              const float* __restrict__ ob,
                                              float* __restrict__ out) {
    __shared__ float sa[256];
    __shared__ float red[4];
    int b = blockIdx.x, j = threadIdx.x;
    sa[j]       = g_t4[b * 256 + j];
    sa[j + 128] = g_t4[b * 256 + 128 + j];
    __syncthreads();
    float acc = b4[j];
#pragma unroll 8
    for (int k = 0; k < 256; k++)
        acc += sa[k] * W4[k * 128 + j];
    float v = fmaxf(acc, 0.f) * oW[j];
#pragma unroll
    for (int off = 16; off; off >>= 1) v += __shfl_down_sync(0xffffffffu, v, off);
    if ((j & 31) == 0) red[j >> 5] = v;
    __syncthreads();
    if (j == 0) out[b] = red[0] + red[1] + red[2] + red[3] + ob[0];
}

// ---------------- host ----------------
static inline dim3 ggrid(long n, int t) { return dim3((unsigned)((n + t - 1) / t)); }

extern "C" void kernel_launch(void* const* d_in, const int* in_sizes, int n_in,
                              void* d_out, int out_size) {
    const float* x      = (const float*)d_in[0];
    const int*   edge   = (const int*)  d_in[1];
    const int*   batch  = (const int*)  d_in[2];
    const int*   target = (const int*)  d_in[3];
    const float* gat_W  = (const float*)d_in[4];
    const float* a_src  = (const float*)d_in[5];
    const float* a_dst  = (const float*)d_in[6];
    const float* gat_b  = (const float*)d_in[7];
    const float* gcn_W  = (const float*)d_in[8];
    const float* gcn_b  = (const float*)d_in[9];
    const float* fcg1_W = (const float*)d_in[10];
    const float* fcg1_b = (const float*)d_in[11];
    const float* fcg2_W = (const float*)d_in[12];
    const float* fcg2_b = (const float*)d_in[13];
    const float* emb    = (const float*)d_in[14];
    const float* cW     = (const float*)d_in[15];
    const float* cb     = (const float*)d_in[16];
    const float* fxt_W  = (const float*)d_in[17];
    const float* fxt_b  = (const float*)d_in[18];
    const float* f1_W   = (const float*)d_in[19];
    const float* f1_b   = (const float*)d_in[20];
    const float* f2_W   = (const float*)d_in[21];
    const float* f2_b   = (const float*)d_in[22];
    const float* f3_W   = (const float*)d_in[23];
    const float* f3_b   = (const float*)d_in[24];
    const float* f4_W   = (const float*)d_in[25];
    const float* f4_b   = (const float*)d_in[26];
    const float* o_W    = (const float*)d_in[27];
    const float* o_b    = (const float*)d_in[28];
    float* out = (float*)d_out;

    float *p_xg, *p_t1, *p_xc, *p_t2, *p_t3, *p_t4, *p_asad;
    __half *p_hH, *p_h2H, *p_Axh, *p_Bah, *p_Ag, *p_Bgh;
    cudaGetSymbolAddress((void**)&p_hH,  g_hH);
    cudaGetSymbolAddress((void**)&p_h2H, g_h2H);
    cudaGetSymbolAddress((void**)&p_asad, g_asad);
    cudaGetSymbolAddress((void**)&p_xg,  g_xg);
    cudaGetSymbolAddress((void**)&p_t1,  g_t1);
    cudaGetSymbolAddress((void**)&p_xc,  g_xc);
    cudaGetSymbolAddress((void**)&p_t2,  g_t2);
    cudaGetSymbolAddress((void**)&p_t3,  g_t3);
    cudaGetSymbolAddress((void**)&p_t4,  g_t4);
    cudaGetSymbolAddress((void**)&p_Axh, g_Axh);
    cudaGetSymbolAddress((void**)&p_Bah, g_Bah);
    cudaGetSymbolAddress((void**)&p_Ag,  g_Ag);
    cudaGetSymbolAddress((void**)&p_Bgh, g_Bgh);

    static cudaStream_t s1, s2;
    static cudaEvent_t eF, e1, e2;
    static int inited = 0;
    if (!inited) {
        cudaStreamCreateWithFlags(&s1, cudaStreamNonBlocking);
        cudaStreamCreateWithFlags(&s2, cudaStreamNonBlocking);
        cudaEventCreateWithFlags(&eF, cudaEventDisableTiming);
        cudaEventCreateWithFlags(&e1, cudaEventDisableTiming);
        cudaEventCreateWithFlags(&e2, cudaEventDisableTiming);
        cudaFuncSetAttribute(gemm_mma, cudaFuncAttributeMaxDynamicSharedMemorySize, GEMM_SMEM);
        inited = 1;
    }

    cudaEventRecord(eF, 0);
    cudaStreamWaitEvent(s1, eF, 0);
    cudaStreamWaitEvent(s2, eF, 0);

    // main: conversions + attn rows
    k_transW<<<dim3(4, 25), 256>>>(gat_W, p_Bah, FF, HID, KPA);
    k_transW<<<dim3(26, 25), 256>>>(gcn_W, p_Bgh, HID, HID, KPG);
    k_prep<<<PB_A + PB_E, 256>>>(x, gat_W, a_src, a_dst);
    // s1: CSR build
    k_count<<<ggrid(ET, 256), 256, 0, s1>>>(edge);
    k_startB<<<ggrid(NN, 256), 256, 0, s1>>>(batch);
    k_scanA<<<NB, 256, 0, s1>>>();
    k_scanB<<<1, 128, 0, s1>>>();
    k_scanC<<<NB, 256, 0, s1>>>();
    // main: GAT GEMM
    gemm_mma<<<dim3(7, 157), 256, GEMM_SMEM>>>(p_Axh, p_Bah, p_hH, NN, NEXT, KPA, KPA / KC, NEXT,
                                               p_asad, HID);
    // s1: scatter
    k_scatter<<<ggrid(ET, 256), 256, 0, s1>>>(edge);
    cudaEventRecord(e1, s1);
    // s2: protein branch
    k_init0<<<1, 128, 0, s2>>>();
    k_Pbias<<<308, 128, 0, s2>>>(emb, cW, fxt_W, cb);
    k_R<<<SEQ, 128, 0, s2>>>(fxt_W);
    k_Y<<<BB, 128, 0, s2>>>(target, fxt_b);
    cudaEventRecord(e2, s2);
    // main: graph branch
    cudaStreamWaitEvent(0, e1, 0);
    k_gat_soft_agg<<<NN, 256>>>(gat_b);
    gemm_mma<<<dim3(7, 157), 256, GEMM_SMEM>>>(p_Ag, p_Bgh, p_h2H, NN, HID, KPG, KPG / KC, HID,
                                               nullptr, 1 << 30);
    k_gcn_agg<<<NN, 256>>>(gcn_b);
    k_pool<<<BB, 256>>>();
    // head
    mlp8<<<dim3(24, 25), 256>>>(p_xg, fcg1_W, p_t1, fcg1_b, BB, 1500, HID, HID, 1500, 0, 1);
    mlp8<<<dim3(2, 25), 256>>>(p_t1, fcg2_W, p_xc, fcg2_b, BB, 128, 1500, 1500, 256, 0, 0);
    cudaStreamWaitEvent(0, e2, 0);
    mlp8<<<dim3(16, 25), 256>>>(p_xc, f1_W, p_t2, f1_b, BB, 1024, 256, 256, 1024, 0, 1);
    mlp8<<<dim3(8, 25), 256>>>(p_t2, f2_W, p_t3, f2_b, BB, 512, 1024, 1024, 512, 0, 1);
    mlp8<<<dim3(4, 25), 256>>>(p_t3, f3_W, p_t4, f3_b, BB, 256, 512, 512, 256, 0, 1);
    k_out2<<<BB, 128>>>(f4_W, f4_b, o_W, o_b, out);
}